// round 15
// baseline (speedup 1.0000x reference)
#include <cuda_runtime.h>
#include <cuda_fp16.h>
#include <cstdint>

// ===========================================================================
// Problem constants
// ===========================================================================
#define NROWS 16384          // B*X*Y*Z latent rows
#define DD    64
#define KCODES 8192
#define SS    4096           // X*Y*Z
#define BB    4
#define OUT_TENSOR_ELEMS (NROWS*DD)

#define MTILE 128            // rows per CTA
#define NT    128            // codes per iteration tile
#define NITER (KCODES/NT)    // 64
#define A_BYTES 16384        // 128 rows x 64 k x 1 term x 2B (fp16 fragments)
#define B_BYTES 16384        // 128 codes x 64 k x 1 term x 2B

// B pre-scaled by 2^13 (exact). Tracking metric: m = acc - 4096*cn
// (argmax m == argmin dist; scale 2^12 exact). Refine recomputes exact dist.
#define CN_SCALE (-4096.0f)

// dynamic smem (gemm): A 16K | B x3 16K | CN x3 512B
#define SM_A   0
#define SM_B(s)  (16384 + (s) * 16384)
#define SM_CN(s) (65536 + (s) * 512)
#define DSMEM_BYTES 67072

// ===========================================================================
// Device scratch (allocation-free rule)
// ===========================================================================
__device__ float g_rn[NROWS];
__device__ float g_cbn[KCODES];
__device__ uint4 g_latfrag[(NROWS / MTILE) * (A_BYTES / 16)];  // 2 MB
__device__ uint4 g_cbfrag[NITER * (B_BYTES / 16)];             // 1 MB
__device__ int2  g_cand[NROWS * 8];   // per row: 8 thread-slots x best-2 idx
__device__ int   g_idx[NROWS];
__device__ float g_losspart[4096];

// ===========================================================================
// Helpers
// ===========================================================================
__device__ __forceinline__ uint32_t smem_u32(const void* p) {
    uint32_t a;
    asm("{ .reg .u64 t; cvta.to.shared.u64 t, %1; cvt.u32.u64 %0, t; }"
        : "=r"(a) : "l"(p));
    return a;
}
__device__ __forceinline__ void cp16(uint32_t dst, const void* src) {
    asm volatile("cp.async.cg.shared.global [%0], [%1], 16;"
                 :: "r"(dst), "l"(src) : "memory");
}
__device__ __forceinline__ void cp4(uint32_t dst, const void* src) {
    asm volatile("cp.async.ca.shared.global [%0], [%1], 4;"
                 :: "r"(dst), "l"(src) : "memory");
}
#define CP_COMMIT() asm volatile("cp.async.commit_group;" ::: "memory")
#define CP_WAIT1()  asm volatile("cp.async.wait_group 1;" ::: "memory")
#define CP_WAIT2()  asm volatile("cp.async.wait_group 2;" ::: "memory")

// fp16 m16n8k16, f32 accumulate (accumulating form)
__device__ __forceinline__ void mma_f16(float* c, const uint32_t* a,
                                        uint32_t b0, uint32_t b1) {
    asm volatile(
        "mma.sync.aligned.m16n8k16.row.col.f32.f16.f16.f32 "
        "{%0,%1,%2,%3}, {%4,%5,%6,%7}, {%8,%9}, {%0,%1,%2,%3};"
        : "+f"(c[0]), "+f"(c[1]), "+f"(c[2]), "+f"(c[3])
        : "r"(a[0]), "r"(a[1]), "r"(a[2]), "r"(a[3]), "r"(b0), "r"(b1));
}

// Non-accumulating form: C = 0 (exact; removes per-iter acc zero-init MOVs)
__device__ __forceinline__ void mma_f16_z(float* c, const uint32_t* a,
                                          uint32_t b0, uint32_t b1) {
    asm volatile(
        "mma.sync.aligned.m16n8k16.row.col.f32.f16.f16.f32 "
        "{%0,%1,%2,%3}, {%4,%5,%6,%7}, {%8,%9}, {%10,%10,%10,%10};"
        : "=f"(c[0]), "=f"(c[1]), "=f"(c[2]), "=f"(c[3])
        : "r"(a[0]), "r"(a[1]), "r"(a[2]), "r"(a[3]), "r"(b0), "r"(b1),
          "f"(0.0f));
}

__device__ __forceinline__ uint32_t pack2h(float a, float b) {
    __half ha = __float2half_rn(a);
    __half hb = __float2half_rn(b);
    return (uint32_t)__half_as_ushort(ha) |
           ((uint32_t)__half_as_ushort(hb) << 16);
}

// ===========================================================================
// K_prep: merged prepA (CTAs 0..127) + prepB (CTAs 128..191).  [R11 verbatim]
// ===========================================================================
__global__ void k_prep(const float* __restrict__ lat,
                       const float* __restrict__ cb) {
    __shared__ float ts[128][65];
    int tid = threadIdx.x;

    if (blockIdx.x < 128) {
        int cta = blockIdx.x;
        int b = cta >> 5;
        int s0 = (cta & 31) * 128;

        {
            int d = tid >> 2;
            int sc = (tid & 3) * 32;
            const float4* src =
                (const float4*)(lat + ((size_t)b * DD + d) * SS + s0 + sc);
#pragma unroll
            for (int i = 0; i < 8; i++) {
                float4 v = src[i];
                ts[sc + 4 * i + 0][d] = v.x;
                ts[sc + 4 * i + 1][d] = v.y;
                ts[sc + 4 * i + 2][d] = v.z;
                ts[sc + 4 * i + 3][d] = v.w;
            }
        }
        __syncthreads();

        // row norm, replicating R1's packed accumulation order bit-for-bit
        if (tid < 128) {
            float rl[4] = {0.f, 0.f, 0.f, 0.f};
            float rh[4] = {0.f, 0.f, 0.f, 0.f};
#pragma unroll
            for (int m = 0; m < 8; m++) {
#pragma unroll
                for (int j = 0; j < 4; j++) {
                    float xl = ts[tid][8 * m + 2 * j];
                    float xh = ts[tid][8 * m + 2 * j + 1];
                    rl[j] = fmaf(xl, xl, rl[j]);
                    rh[j] = fmaf(xh, xh, rh[j]);
                }
            }
            float slo = (rl[0] + rl[1]) + (rl[2] + rl[3]);
            float shi = (rh[0] + rh[1]) + (rh[2] + rh[3]);
            g_rn[cta * MTILE + tid] = slo + shi;
        }

        // A fragments (term 1 only): blocks (wm:4)(s:4)(i:2) x 32 lanes
#pragma unroll
        for (int f4 = 0; f4 < 4; f4++) {
            int f = f4 * 256 + tid;
            int wm = f >> 8;
            int s = (f >> 6) & 3;
            int ii = (f >> 5) & 1;
            int lane = f & 31;
            int r0 = wm * 32 + ii * 16 + (lane >> 2);
            int k0 = s * 16 + (lane & 3) * 2;
            uint4 o;
            uint32_t* po = &o.x;
#pragma unroll
            for (int q = 0; q < 4; q++) {
                int dr = (q & 1) * 8;
                int dk = (q >> 1) * 8;
                po[q] = pack2h(ts[r0 + dr][k0 + dk], ts[r0 + dr][k0 + dk + 1]);
            }
            g_latfrag[cta * 1024 + f] = o;
        }
    } else {
        int tile = blockIdx.x - 128;
        int kc0 = tile * NT;

        {
            int code = tid >> 1;
            int half = tid & 1;
            const float4* src =
                (const float4*)(cb + (size_t)(kc0 + code) * DD) + half * 8;
#pragma unroll
            for (int i = 0; i < 8; i++) {
                float4 v = src[i];
                ts[code][half * 32 + 4 * i + 0] = v.x;
                ts[code][half * 32 + 4 * i + 1] = v.y;
                ts[code][half * 32 + 4 * i + 2] = v.z;
                ts[code][half * 32 + 4 * i + 3] = v.w;
            }
        }
        __syncthreads();

        if (tid < 128) {
            float a[4] = {0.f, 0.f, 0.f, 0.f};
#pragma unroll
            for (int i = 0; i < 16; i++) {
#pragma unroll
                for (int j = 0; j < 4; j++) {
                    float v = ts[tid][4 * i + j];
                    a[j] = fmaf(v, v, a[j]);
                }
            }
            g_cbn[kc0 + tid] = (a[0] + a[1]) + (a[2] + a[3]);
        }

        // B fragments (term 1 only, scaled 2^13): blocks (wn:2)(s:4)(p:4)
#pragma unroll
        for (int f4 = 0; f4 < 4; f4++) {
            int f = f4 * 256 + tid;
            int wn = f >> 9;
            int s = (f >> 7) & 3;
            int p = (f >> 5) & 3;
            int lane = f & 31;
            int g = lane >> 2;
            int k0 = s * 16 + (lane & 3) * 2;
            uint4 o;
            uint32_t* po = &o.x;
#pragma unroll
            for (int c = 0; c < 4; c++) {
                int j = 2 * p + (c >> 1);
                int dk = ((c & 1) ? 8 : 0);
                int code = wn * 64 + j * 8 + g;
                po[c] = pack2h(ts[code][k0 + dk] * 8192.0f,
                               ts[code][k0 + dk + 1] * 8192.0f);
            }
            g_cbfrag[tile * 1024 + f] = o;
        }
    }
}

// ===========================================================================
// K1: phase-1 fp16 GEMM + best-2 candidate tracking.
// Changes vs R14 (both value-preserving):
//  - s=0 MMA block uses non-accumulating form (C=0) -> no acc zero-init.
//  - Pair-max screen: fmaxf(m0,m1) vs v2 gates the (rare) exact ordered
//    update path; capture results bit-identical to R14.
// ===========================================================================
__global__ void __launch_bounds__(256, 1) k_gemm_cand() {
    extern __shared__ char sm[];
    uint32_t sbase = smem_u32(sm);
    int tid = threadIdx.x;
    int lane = tid & 31;
    int wid = tid >> 5;
    int wm = wid >> 1;               // rows wm*32..+32
    int wn = wid & 1;                // cols wn*64..+64
    int cta = blockIdx.x;

    // ---- prologue: A (g0), B tile0+CN0 (g1), B tile1+CN1 (g2) ----
    {
        const char* asrc = (const char*)g_latfrag + (size_t)cta * A_BYTES;
#pragma unroll
        for (int c = 0; c < 4; c++)
            cp16(sbase + SM_A + (c * 256 + tid) * 16, asrc + (c * 256 + tid) * 16);
        CP_COMMIT();
        const char* bsrc = (const char*)g_cbfrag;
#pragma unroll
        for (int c = 0; c < 4; c++)
            cp16(sbase + SM_B(0) + (c * 256 + tid) * 16, bsrc + (c * 256 + tid) * 16);
        if (tid < 128) cp4(sbase + SM_CN(0) + tid * 4, g_cbn + tid);
        CP_COMMIT();
#pragma unroll
        for (int c = 0; c < 4; c++)
            cp16(sbase + SM_B(1) + (c * 256 + tid) * 16,
                 bsrc + B_BYTES + (c * 256 + tid) * 16);
        if (tid < 128) cp4(sbase + SM_CN(1) + tid * 4, g_cbn + 128 + tid);
        CP_COMMIT();
    }

    // ---- wait for A, cache 8 A fragments (term 1) in registers ----
    CP_WAIT2();
    __syncthreads();
    uint32_t af[4][2][4];            // [s][i][4regs]
    {
        uint32_t a_base = sbase + SM_A + (uint32_t)wm * 4096 + lane * 16;
#pragma unroll
        for (int s = 0; s < 4; s++)
#pragma unroll
            for (int i = 0; i < 2; i++) {
                asm volatile("ld.shared.v4.b32 {%0,%1,%2,%3}, [%4];"
                    : "=r"(af[s][i][0]), "=r"(af[s][i][1]),
                      "=r"(af[s][i][2]), "=r"(af[s][i][3])
                    : "r"(a_base + (uint32_t)(s * 2 + i) * 512u));
            }
    }

    // best-2 per slot (metric m, maximized; index kept for refine)
    float v1[4] = {-3.4e38f, -3.4e38f, -3.4e38f, -3.4e38f};
    float v2[4] = {-3.4e38f, -3.4e38f, -3.4e38f, -3.4e38f};
    int   i1[4] = {0, 0, 0, 0};
    int   i2[4] = {0, 0, 0, 0};
    uint32_t cn_off = (uint32_t)(wn * 64 + (lane & 3) * 2) * 4;

    int sel = 0;
    for (int t = 0; t < NITER; t++) {
        CP_WAIT1();
        __syncthreads();

        int psel = sel + 2; if (psel >= 3) psel -= 3;
        if (t + 2 < NITER) {
            const char* bsrc = (const char*)g_cbfrag + (size_t)(t + 2) * B_BYTES;
            uint32_t dst = sbase + SM_B(psel);
#pragma unroll
            for (int c = 0; c < 4; c++)
                cp16(dst + (c * 256 + tid) * 16, bsrc + (c * 256 + tid) * 16);
            if (tid < 128)
                cp4(sbase + SM_CN(psel) + tid * 4, g_cbn + (t + 2) * NT + tid);
        }
        CP_COMMIT();

        uint32_t b_base = sbase + SM_B(sel) + (uint32_t)wn * 8192 + lane * 16;
        uint32_t cn_base = sbase + SM_CN(sel) + cn_off;

        float acc[2][8][4];

        // s = 0: non-accumulating MMAs (C = 0) — defines acc, no init needed
        {
            uint32_t bw[4][4];
#pragma unroll
            for (int p = 0; p < 4; p++)
                asm volatile("ld.shared.v4.b32 {%0,%1,%2,%3}, [%4];"
                    : "=r"(bw[p][0]), "=r"(bw[p][1]),
                      "=r"(bw[p][2]), "=r"(bw[p][3])
                    : "r"(b_base + (uint32_t)p * 512u));
#pragma unroll
            for (int p = 0; p < 4; p++) {
                mma_f16_z(acc[0][2 * p],     af[0][0], bw[p][0], bw[p][1]);
                mma_f16_z(acc[0][2 * p + 1], af[0][0], bw[p][2], bw[p][3]);
                mma_f16_z(acc[1][2 * p],     af[0][1], bw[p][0], bw[p][1]);
                mma_f16_z(acc[1][2 * p + 1], af[0][1], bw[p][2], bw[p][3]);
            }
        }
        // s = 1..3: accumulate
#pragma unroll
        for (int s = 1; s < 4; s++) {
            uint32_t bw[4][4];
#pragma unroll
            for (int p = 0; p < 4; p++)
                asm volatile("ld.shared.v4.b32 {%0,%1,%2,%3}, [%4];"
                    : "=r"(bw[p][0]), "=r"(bw[p][1]),
                      "=r"(bw[p][2]), "=r"(bw[p][3])
                    : "r"(b_base + (uint32_t)(s * 4 + p) * 512u));
#pragma unroll
            for (int p = 0; p < 4; p++) {
                mma_f16(acc[0][2 * p],     af[s][0], bw[p][0], bw[p][1]);
                mma_f16(acc[0][2 * p + 1], af[s][0], bw[p][2], bw[p][3]);
                mma_f16(acc[1][2 * p],     af[s][1], bw[p][0], bw[p][1]);
                mma_f16(acc[1][2 * p + 1], af[s][1], bw[p][2], bw[p][3]);
            }
        }

        // best-2 tracking with pair-max screen (capture identical to R14)
        int kb = t * NT + wn * 64 + 2 * (lane & 3);
#pragma unroll
        for (int j = 0; j < 8; j++) {
            float2 cn2;
            asm volatile("ld.shared.v2.b32 {%0,%1}, [%2];"
                : "=f"(cn2.x), "=f"(cn2.y) : "r"(cn_base + j * 32u));
            int kbj = kb + j * 8;
#pragma unroll
            for (int i = 0; i < 2; i++) {
#pragma unroll
                for (int vp = 0; vp < 2; vp++) {
                    int slot = i * 2 + vp;
                    float m0 = fmaf(CN_SCALE, cn2.x, acc[i][j][2 * vp]);
                    float m1 = fmaf(CN_SCALE, cn2.y, acc[i][j][2 * vp + 1]);
                    float mm = fmaxf(m0, m1);
                    if (mm > v2[slot]) {
                        // exact ordered updates (same sequence as R14)
                        if (m0 > v2[slot]) {
                            if (m0 > v1[slot]) {
                                v2[slot] = v1[slot]; i2[slot] = i1[slot];
                                v1[slot] = m0;       i1[slot] = kbj;
                            } else {
                                v2[slot] = m0;       i2[slot] = kbj;
                            }
                        }
                        if (m1 > v2[slot]) {
                            if (m1 > v1[slot]) {
                                v2[slot] = v1[slot]; i2[slot] = i1[slot];
                                v1[slot] = m1;       i1[slot] = kbj + 1;
                            } else {
                                v2[slot] = m1;       i2[slot] = kbj + 1;
                            }
                        }
                    }
                }
            }
        }

        sel++; if (sel >= 3) sel -= 3;
    }

    // ---- emit candidates: per slot, 2 indices ----
    int slotcol = wn * 4 + (lane & 3);
#pragma unroll
    for (int i = 0; i < 2; i++)
#pragma unroll
        for (int h = 0; h < 2; h++) {
            int row = cta * MTILE + wm * 32 + i * 16 + (lane >> 2) + h * 8;
            int slot = i * 2 + h;
            g_cand[row * 8 + slotcol] = make_int2(i1[slot], i2[slot]);
        }
}

// ===========================================================================
// K2: exact refinement, 8 threads per row.  [R12 verbatim]
// ===========================================================================
__global__ void __launch_bounds__(256) k_refine(const float* __restrict__ lat,
                                                const float* __restrict__ cb) {
    int tid = threadIdx.x;
    int grp = tid & 7;                       // candidate slot 0..7
    int n = blockIdx.x * 32 + (tid >> 3);    // row
    int s = n & (SS - 1);
    int b = n >> 12;

    float x[DD];
#pragma unroll
    for (int d = 0; d < DD; d++)
        x[d] = lat[((size_t)b * DD + d) * SS + s];

    float rn = g_rn[n];
    int2 c2 = g_cand[n * 8 + grp];

    unsigned long long best = 0xFFFFFFFFFFFFFFFFull;
#pragma unroll
    for (int c = 0; c < 2; c++) {
        int idx = (c == 0) ? c2.x : c2.y;
        const float4* e4 = (const float4*)(cb + (size_t)idx * DD);
        float a0 = 0.f, a1 = 0.f, a2 = 0.f, a3 = 0.f;
#pragma unroll
        for (int q = 0; q < 16; q++) {
            float4 e = e4[q];
            a0 = fmaf(x[4 * q + 0], e.x, a0);
            a1 = fmaf(x[4 * q + 1], e.y, a1);
            a2 = fmaf(x[4 * q + 2], e.z, a2);
            a3 = fmaf(x[4 * q + 3], e.w, a3);
        }
        float dot = (a0 + a1) + (a2 + a3);
        float dist = fmaf(-2.f, dot, rn + g_cbn[idx]);
        unsigned long long key =
            ((unsigned long long)__float_as_uint(dist) << 32) | (unsigned)idx;
        if (key < best) best = key;
    }

#pragma unroll
    for (int o = 4; o > 0; o >>= 1) {
        unsigned long long other = __shfl_xor_sync(0xffffffffu, best, o);
        if (other < best) best = other;
    }
    if (grp == 0) g_idx[n] = (int)(unsigned)best;
}

// ===========================================================================
// K3: output gather (native layout, coalesced) + block loss partials (R1)
// ===========================================================================
__global__ void k_outloss(const float* __restrict__ lat,
                          const float* __restrict__ cb,
                          float* __restrict__ out) {
    int e = blockIdx.x * 256 + threadIdx.x;
    int s = e & (SS - 1);
    int bd = e >> 12;
    int d = bd & (DD - 1);
    int b = bd >> 6;
    int n = b * SS + s;
    int idx = g_idx[n];
    float q = cb[(size_t)idx * DD + d];
    float l = lat[e];
    out[e] = q;
    float df = q - l;
    float v = df * df;
#pragma unroll
    for (int o = 16; o > 0; o >>= 1) v += __shfl_down_sync(0xffffffffu, v, o);
    __shared__ float red[8];
    int w = threadIdx.x >> 5, ln = threadIdx.x & 31;
    if (ln == 0) red[w] = v;
    __syncthreads();
    if (threadIdx.x < 32) {
        float x = (threadIdx.x < 8) ? red[threadIdx.x] : 0.f;
#pragma unroll
        for (int o = 4; o > 0; o >>= 1) x += __shfl_down_sync(0xffffffffu, x, o);
        if (threadIdx.x == 0) g_losspart[blockIdx.x] = x;
    }
}

// ===========================================================================
// K4: final fixed-order reduce (R1)
// ===========================================================================
__global__ void k_final(const float* __restrict__ vqw,
                        float* __restrict__ out, int out_size) {
    __shared__ float sm2[256];
    int tid = threadIdx.x;
    float a = 0.f;
#pragma unroll
    for (int i = 0; i < 16; i++) a += g_losspart[tid * 16 + i];
    sm2[tid] = a;
    __syncthreads();
    for (int o = 128; o > 0; o >>= 1) {
        if (tid < o) sm2[tid] += sm2[tid + o];
        __syncthreads();
    }
    if (tid == 0 && out_size > OUT_TENSOR_ELEMS) {
        float w = vqw[0];
        out[out_size - 1] = sm2[0] * (1.f + w) * (1.f / (float)OUT_TENSOR_ELEMS);
    }
}

// ===========================================================================
extern "C" void kernel_launch(void* const* d_in, const int* in_sizes, int n_in,
                              void* d_out, int out_size) {
    const float* lat = (const float*)d_in[0];
    const float* vqw = (const float*)d_in[1];
    const float* cb  = (const float*)d_in[2];
    float* out = (float*)d_out;

    static int s_attr = 0;
    if (!s_attr) {
        cudaFuncSetAttribute(k_gemm_cand,
                             cudaFuncAttributeMaxDynamicSharedMemorySize,
                             DSMEM_BYTES);
        s_attr = 1;
    }

    k_prep<<<192, 256>>>(lat, cb);
    k_gemm_cand<<<NROWS / MTILE, 256, DSMEM_BYTES>>>();
    k_refine<<<NROWS / 32, 256>>>(lat, cb);
    k_outloss<<<OUT_TENSOR_ELEMS / 256, 256>>>(lat, cb, out);
    k_final<<<1, 256>>>(vqw, out, out_size);
}

// round 16
// speedup vs baseline: 1.3884x; 1.3884x over previous
#include <cuda_runtime.h>
#include <cuda_fp16.h>
#include <cstdint>

// ===========================================================================
// Problem constants
// ===========================================================================
#define NROWS 16384          // B*X*Y*Z latent rows
#define DD    64
#define KCODES 8192
#define SS    4096           // X*Y*Z
#define BB    4
#define OUT_TENSOR_ELEMS (NROWS*DD)

#define MTILE 128            // rows per CTA
#define NT    128            // codes per iteration tile
#define NITER (KCODES/NT)    // 64
#define A_BYTES 16384        // 128 rows x 64 k x 1 term x 2B (fp16 fragments)
#define B_BYTES 16384        // 128 codes x 64 k x 1 term x 2B

// B pre-scaled by 2^13 (exact). Tracking metric: m = acc - 4096*cn
// (argmax m == argmin dist; scale 2^12 exact). Refine recomputes exact dist.
#define CN_SCALE (-4096.0f)

// dynamic smem (gemm): A 16K | B x3 16K | CN x3 512B
#define SM_A   0
#define SM_B(s)  (16384 + (s) * 16384)
#define SM_CN(s) (65536 + (s) * 512)
#define DSMEM_BYTES 67072

// ===========================================================================
// Device scratch (allocation-free rule)
// ===========================================================================
__device__ float g_rn[NROWS];
__device__ float g_cbn[KCODES];
__device__ uint4 g_latfrag[(NROWS / MTILE) * (A_BYTES / 16)];  // 2 MB
__device__ uint4 g_cbfrag[NITER * (B_BYTES / 16)];             // 1 MB
__device__ int2  g_cand[NROWS * 8];   // per row: 8 thread-slots x best-2 idx
__device__ int   g_idx[NROWS];
__device__ float g_losspart[4096];

// ===========================================================================
// Helpers
// ===========================================================================
__device__ __forceinline__ uint32_t smem_u32(const void* p) {
    uint32_t a;
    asm("{ .reg .u64 t; cvta.to.shared.u64 t, %1; cvt.u32.u64 %0, t; }"
        : "=r"(a) : "l"(p));
    return a;
}
__device__ __forceinline__ void cp16(uint32_t dst, const void* src) {
    asm volatile("cp.async.cg.shared.global [%0], [%1], 16;"
                 :: "r"(dst), "l"(src) : "memory");
}
__device__ __forceinline__ void cp4(uint32_t dst, const void* src) {
    asm volatile("cp.async.ca.shared.global [%0], [%1], 4;"
                 :: "r"(dst), "l"(src) : "memory");
}
#define CP_COMMIT() asm volatile("cp.async.commit_group;" ::: "memory")
#define CP_WAIT1()  asm volatile("cp.async.wait_group 1;" ::: "memory")
#define CP_WAIT2()  asm volatile("cp.async.wait_group 2;" ::: "memory")

// fp16 m16n8k16, f32 accumulate (accumulating form)
__device__ __forceinline__ void mma_f16(float* c, const uint32_t* a,
                                        uint32_t b0, uint32_t b1) {
    asm volatile(
        "mma.sync.aligned.m16n8k16.row.col.f32.f16.f16.f32 "
        "{%0,%1,%2,%3}, {%4,%5,%6,%7}, {%8,%9}, {%0,%1,%2,%3};"
        : "+f"(c[0]), "+f"(c[1]), "+f"(c[2]), "+f"(c[3])
        : "r"(a[0]), "r"(a[1]), "r"(a[2]), "r"(a[3]), "r"(b0), "r"(b1));
}

// Non-accumulating form: C = 0 (exact 0+x=x; removes per-iter acc zero-init)
__device__ __forceinline__ void mma_f16_z(float* c, const uint32_t* a,
                                          uint32_t b0, uint32_t b1) {
    asm volatile(
        "mma.sync.aligned.m16n8k16.row.col.f32.f16.f16.f32 "
        "{%0,%1,%2,%3}, {%4,%5,%6,%7}, {%8,%9}, {%10,%10,%10,%10};"
        : "=f"(c[0]), "=f"(c[1]), "=f"(c[2]), "=f"(c[3])
        : "r"(a[0]), "r"(a[1]), "r"(a[2]), "r"(a[3]), "r"(b0), "r"(b1),
          "f"(0.0f));
}

__device__ __forceinline__ uint32_t pack2h(float a, float b) {
    __half ha = __float2half_rn(a);
    __half hb = __float2half_rn(b);
    return (uint32_t)__half_as_ushort(ha) |
           ((uint32_t)__half_as_ushort(hb) << 16);
}

// ===========================================================================
// K_prep: merged prepA (CTAs 0..127) + prepB (CTAs 128..191).  [R11 verbatim]
// ===========================================================================
__global__ void k_prep(const float* __restrict__ lat,
                       const float* __restrict__ cb) {
    __shared__ float ts[128][65];
    int tid = threadIdx.x;

    if (blockIdx.x < 128) {
        int cta = blockIdx.x;
        int b = cta >> 5;
        int s0 = (cta & 31) * 128;

        {
            int d = tid >> 2;
            int sc = (tid & 3) * 32;
            const float4* src =
                (const float4*)(lat + ((size_t)b * DD + d) * SS + s0 + sc);
#pragma unroll
            for (int i = 0; i < 8; i++) {
                float4 v = src[i];
                ts[sc + 4 * i + 0][d] = v.x;
                ts[sc + 4 * i + 1][d] = v.y;
                ts[sc + 4 * i + 2][d] = v.z;
                ts[sc + 4 * i + 3][d] = v.w;
            }
        }
        __syncthreads();

        // row norm, replicating R1's packed accumulation order bit-for-bit
        if (tid < 128) {
            float rl[4] = {0.f, 0.f, 0.f, 0.f};
            float rh[4] = {0.f, 0.f, 0.f, 0.f};
#pragma unroll
            for (int m = 0; m < 8; m++) {
#pragma unroll
                for (int j = 0; j < 4; j++) {
                    float xl = ts[tid][8 * m + 2 * j];
                    float xh = ts[tid][8 * m + 2 * j + 1];
                    rl[j] = fmaf(xl, xl, rl[j]);
                    rh[j] = fmaf(xh, xh, rh[j]);
                }
            }
            float slo = (rl[0] + rl[1]) + (rl[2] + rl[3]);
            float shi = (rh[0] + rh[1]) + (rh[2] + rh[3]);
            g_rn[cta * MTILE + tid] = slo + shi;
        }

        // A fragments (term 1 only): blocks (wm:4)(s:4)(i:2) x 32 lanes
#pragma unroll
        for (int f4 = 0; f4 < 4; f4++) {
            int f = f4 * 256 + tid;
            int wm = f >> 8;
            int s = (f >> 6) & 3;
            int ii = (f >> 5) & 1;
            int lane = f & 31;
            int r0 = wm * 32 + ii * 16 + (lane >> 2);
            int k0 = s * 16 + (lane & 3) * 2;
            uint4 o;
            uint32_t* po = &o.x;
#pragma unroll
            for (int q = 0; q < 4; q++) {
                int dr = (q & 1) * 8;
                int dk = (q >> 1) * 8;
                po[q] = pack2h(ts[r0 + dr][k0 + dk], ts[r0 + dr][k0 + dk + 1]);
            }
            g_latfrag[cta * 1024 + f] = o;
        }
    } else {
        int tile = blockIdx.x - 128;
        int kc0 = tile * NT;

        {
            int code = tid >> 1;
            int half = tid & 1;
            const float4* src =
                (const float4*)(cb + (size_t)(kc0 + code) * DD) + half * 8;
#pragma unroll
            for (int i = 0; i < 8; i++) {
                float4 v = src[i];
                ts[code][half * 32 + 4 * i + 0] = v.x;
                ts[code][half * 32 + 4 * i + 1] = v.y;
                ts[code][half * 32 + 4 * i + 2] = v.z;
                ts[code][half * 32 + 4 * i + 3] = v.w;
            }
        }
        __syncthreads();

        if (tid < 128) {
            float a[4] = {0.f, 0.f, 0.f, 0.f};
#pragma unroll
            for (int i = 0; i < 16; i++) {
#pragma unroll
                for (int j = 0; j < 4; j++) {
                    float v = ts[tid][4 * i + j];
                    a[j] = fmaf(v, v, a[j]);
                }
            }
            g_cbn[kc0 + tid] = (a[0] + a[1]) + (a[2] + a[3]);
        }

        // B fragments (term 1 only, scaled 2^13): blocks (wn:2)(s:4)(p:4)
#pragma unroll
        for (int f4 = 0; f4 < 4; f4++) {
            int f = f4 * 256 + tid;
            int wn = f >> 9;
            int s = (f >> 7) & 3;
            int p = (f >> 5) & 3;
            int lane = f & 31;
            int g = lane >> 2;
            int k0 = s * 16 + (lane & 3) * 2;
            uint4 o;
            uint32_t* po = &o.x;
#pragma unroll
            for (int c = 0; c < 4; c++) {
                int j = 2 * p + (c >> 1);
                int dk = ((c & 1) ? 8 : 0);
                int code = wn * 64 + j * 8 + g;
                po[c] = pack2h(ts[code][k0 + dk] * 8192.0f,
                               ts[code][k0 + dk + 1] * 8192.0f);
            }
            g_cbfrag[tile * 1024 + f] = o;
        }
    }
}

// ===========================================================================
// K1: phase-1 fp16 GEMM + best-2 candidate tracking.
// R14 verbatim EXCEPT: s=0 MMA block is non-accumulating (C=0), which
// removes the per-iteration accumulator zero-init. Epilogue = R14's.
// ===========================================================================
__global__ void __launch_bounds__(256, 1) k_gemm_cand() {
    extern __shared__ char sm[];
    uint32_t sbase = smem_u32(sm);
    int tid = threadIdx.x;
    int lane = tid & 31;
    int wid = tid >> 5;
    int wm = wid >> 1;               // rows wm*32..+32
    int wn = wid & 1;                // cols wn*64..+64
    int cta = blockIdx.x;

    // ---- prologue: A (g0), B tile0+CN0 (g1), B tile1+CN1 (g2) ----
    {
        const char* asrc = (const char*)g_latfrag + (size_t)cta * A_BYTES;
#pragma unroll
        for (int c = 0; c < 4; c++)
            cp16(sbase + SM_A + (c * 256 + tid) * 16, asrc + (c * 256 + tid) * 16);
        CP_COMMIT();
        const char* bsrc = (const char*)g_cbfrag;
#pragma unroll
        for (int c = 0; c < 4; c++)
            cp16(sbase + SM_B(0) + (c * 256 + tid) * 16, bsrc + (c * 256 + tid) * 16);
        if (tid < 128) cp4(sbase + SM_CN(0) + tid * 4, g_cbn + tid);
        CP_COMMIT();
#pragma unroll
        for (int c = 0; c < 4; c++)
            cp16(sbase + SM_B(1) + (c * 256 + tid) * 16,
                 bsrc + B_BYTES + (c * 256 + tid) * 16);
        if (tid < 128) cp4(sbase + SM_CN(1) + tid * 4, g_cbn + 128 + tid);
        CP_COMMIT();
    }

    // ---- wait for A, cache 8 A fragments (term 1) in registers ----
    CP_WAIT2();
    __syncthreads();
    uint32_t af[4][2][4];            // [s][i][4regs]
    {
        uint32_t a_base = sbase + SM_A + (uint32_t)wm * 4096 + lane * 16;
#pragma unroll
        for (int s = 0; s < 4; s++)
#pragma unroll
            for (int i = 0; i < 2; i++) {
                asm volatile("ld.shared.v4.b32 {%0,%1,%2,%3}, [%4];"
                    : "=r"(af[s][i][0]), "=r"(af[s][i][1]),
                      "=r"(af[s][i][2]), "=r"(af[s][i][3])
                    : "r"(a_base + (uint32_t)(s * 2 + i) * 512u));
            }
    }

    // best-2 per slot (metric m, maximized; index kept for refine)
    float v1[4] = {-3.4e38f, -3.4e38f, -3.4e38f, -3.4e38f};
    float v2[4] = {-3.4e38f, -3.4e38f, -3.4e38f, -3.4e38f};
    int   i1[4] = {0, 0, 0, 0};
    int   i2[4] = {0, 0, 0, 0};
    uint32_t cn_off = (uint32_t)(wn * 64 + (lane & 3) * 2) * 4;

    int sel = 0;
    for (int t = 0; t < NITER; t++) {
        CP_WAIT1();
        __syncthreads();

        int psel = sel + 2; if (psel >= 3) psel -= 3;
        if (t + 2 < NITER) {
            const char* bsrc = (const char*)g_cbfrag + (size_t)(t + 2) * B_BYTES;
            uint32_t dst = sbase + SM_B(psel);
#pragma unroll
            for (int c = 0; c < 4; c++)
                cp16(dst + (c * 256 + tid) * 16, bsrc + (c * 256 + tid) * 16);
            if (tid < 128)
                cp4(sbase + SM_CN(psel) + tid * 4, g_cbn + (t + 2) * NT + tid);
        }
        CP_COMMIT();

        uint32_t b_base = sbase + SM_B(sel) + (uint32_t)wn * 8192 + lane * 16;
        uint32_t cn_base = sbase + SM_CN(sel) + cn_off;

        float acc[2][8][4];

        // s = 0: non-accumulating MMAs (C = 0) — defines acc, no init needed
        {
            uint32_t bw[4][4];
#pragma unroll
            for (int p = 0; p < 4; p++)
                asm volatile("ld.shared.v4.b32 {%0,%1,%2,%3}, [%4];"
                    : "=r"(bw[p][0]), "=r"(bw[p][1]),
                      "=r"(bw[p][2]), "=r"(bw[p][3])
                    : "r"(b_base + (uint32_t)p * 512u));
#pragma unroll
            for (int p = 0; p < 4; p++) {
                mma_f16_z(acc[0][2 * p],     af[0][0], bw[p][0], bw[p][1]);
                mma_f16_z(acc[0][2 * p + 1], af[0][0], bw[p][2], bw[p][3]);
                mma_f16_z(acc[1][2 * p],     af[0][1], bw[p][0], bw[p][1]);
                mma_f16_z(acc[1][2 * p + 1], af[0][1], bw[p][2], bw[p][3]);
            }
        }
        // s = 1..3: accumulate
#pragma unroll
        for (int s = 1; s < 4; s++) {
            uint32_t bw[4][4];
#pragma unroll
            for (int p = 0; p < 4; p++)
                asm volatile("ld.shared.v4.b32 {%0,%1,%2,%3}, [%4];"
                    : "=r"(bw[p][0]), "=r"(bw[p][1]),
                      "=r"(bw[p][2]), "=r"(bw[p][3])
                    : "r"(b_base + (uint32_t)(s * 4 + p) * 512u));
#pragma unroll
            for (int p = 0; p < 4; p++) {
                mma_f16(acc[0][2 * p],     af[s][0], bw[p][0], bw[p][1]);
                mma_f16(acc[0][2 * p + 1], af[s][0], bw[p][2], bw[p][3]);
                mma_f16(acc[1][2 * p],     af[s][1], bw[p][0], bw[p][1]);
                mma_f16(acc[1][2 * p + 1], af[s][1], bw[p][2], bw[p][3]);
            }
        }

        // best-2 tracking: max of m = fmaf(-4096, cn, acc)   [R14 verbatim]
        int kb = t * NT + wn * 64 + 2 * (lane & 3);
#pragma unroll
        for (int j = 0; j < 8; j++) {
            float2 cn2;
            asm volatile("ld.shared.v2.b32 {%0,%1}, [%2];"
                : "=f"(cn2.x), "=f"(cn2.y) : "r"(cn_base + j * 32u));
            int kbj = kb + j * 8;
#pragma unroll
            for (int i = 0; i < 2; i++) {
#pragma unroll
                for (int v = 0; v < 4; v++) {
                    float cn = (v & 1) ? cn2.y : cn2.x;
                    int slot = i * 2 + (v >> 1);
                    float m = fmaf(CN_SCALE, cn, acc[i][j][v]);
                    int idx = kbj + (v & 1);
                    if (m > v2[slot]) {
                        if (m > v1[slot]) {
                            v2[slot] = v1[slot]; i2[slot] = i1[slot];
                            v1[slot] = m;        i1[slot] = idx;
                        } else {
                            v2[slot] = m;        i2[slot] = idx;
                        }
                    }
                }
            }
        }

        sel++; if (sel >= 3) sel -= 3;
    }

    // ---- emit candidates: per slot, 2 indices ----
    int slotcol = wn * 4 + (lane & 3);
#pragma unroll
    for (int i = 0; i < 2; i++)
#pragma unroll
        for (int h = 0; h < 2; h++) {
            int row = cta * MTILE + wm * 32 + i * 16 + (lane >> 2) + h * 8;
            int slot = i * 2 + h;
            g_cand[row * 8 + slotcol] = make_int2(i1[slot], i2[slot]);
        }
}

// ===========================================================================
// K2: exact refinement, 8 threads per row.  [R12 verbatim]
// ===========================================================================
__global__ void __launch_bounds__(256) k_refine(const float* __restrict__ lat,
                                                const float* __restrict__ cb) {
    int tid = threadIdx.x;
    int grp = tid & 7;                       // candidate slot 0..7
    int n = blockIdx.x * 32 + (tid >> 3);    // row
    int s = n & (SS - 1);
    int b = n >> 12;

    float x[DD];
#pragma unroll
    for (int d = 0; d < DD; d++)
        x[d] = lat[((size_t)b * DD + d) * SS + s];

    float rn = g_rn[n];
    int2 c2 = g_cand[n * 8 + grp];

    unsigned long long best = 0xFFFFFFFFFFFFFFFFull;
#pragma unroll
    for (int c = 0; c < 2; c++) {
        int idx = (c == 0) ? c2.x : c2.y;
        const float4* e4 = (const float4*)(cb + (size_t)idx * DD);
        float a0 = 0.f, a1 = 0.f, a2 = 0.f, a3 = 0.f;
#pragma unroll
        for (int q = 0; q < 16; q++) {
            float4 e = e4[q];
            a0 = fmaf(x[4 * q + 0], e.x, a0);
            a1 = fmaf(x[4 * q + 1], e.y, a1);
            a2 = fmaf(x[4 * q + 2], e.z, a2);
            a3 = fmaf(x[4 * q + 3], e.w, a3);
        }
        float dot = (a0 + a1) + (a2 + a3);
        float dist = fmaf(-2.f, dot, rn + g_cbn[idx]);
        unsigned long long key =
            ((unsigned long long)__float_as_uint(dist) << 32) | (unsigned)idx;
        if (key < best) best = key;
    }

#pragma unroll
    for (int o = 4; o > 0; o >>= 1) {
        unsigned long long other = __shfl_xor_sync(0xffffffffu, best, o);
        if (other < best) best = other;
    }
    if (grp == 0) g_idx[n] = (int)(unsigned)best;
}

// ===========================================================================
// K3: output gather (native layout, coalesced) + block loss partials (R1)
// ===========================================================================
__global__ void k_outloss(const float* __restrict__ lat,
                          const float* __restrict__ cb,
                          float* __restrict__ out) {
    int e = blockIdx.x * 256 + threadIdx.x;
    int s = e & (SS - 1);
    int bd = e >> 12;
    int d = bd & (DD - 1);
    int b = bd >> 6;
    int n = b * SS + s;
    int idx = g_idx[n];
    float q = cb[(size_t)idx * DD + d];
    float l = lat[e];
    out[e] = q;
    float df = q - l;
    float v = df * df;
#pragma unroll
    for (int o = 16; o > 0; o >>= 1) v += __shfl_down_sync(0xffffffffu, v, o);
    __shared__ float red[8];
    int w = threadIdx.x >> 5, ln = threadIdx.x & 31;
    if (ln == 0) red[w] = v;
    __syncthreads();
    if (threadIdx.x < 32) {
        float x = (threadIdx.x < 8) ? red[threadIdx.x] : 0.f;
#pragma unroll
        for (int o = 4; o > 0; o >>= 1) x += __shfl_down_sync(0xffffffffu, x, o);
        if (threadIdx.x == 0) g_losspart[blockIdx.x] = x;
    }
}

// ===========================================================================
// K4: final fixed-order reduce (R1)
// ===========================================================================
__global__ void k_final(const float* __restrict__ vqw,
                        float* __restrict__ out, int out_size) {
    __shared__ float sm2[256];
    int tid = threadIdx.x;
    float a = 0.f;
#pragma unroll
    for (int i = 0; i < 16; i++) a += g_losspart[tid * 16 + i];
    sm2[tid] = a;
    __syncthreads();
    for (int o = 128; o > 0; o >>= 1) {
        if (tid < o) sm2[tid] += sm2[tid + o];
        __syncthreads();
    }
    if (tid == 0 && out_size > OUT_TENSOR_ELEMS) {
        float w = vqw[0];
        out[out_size - 1] = sm2[0] * (1.f + w) * (1.f / (float)OUT_TENSOR_ELEMS);
    }
}

// ===========================================================================
extern "C" void kernel_launch(void* const* d_in, const int* in_sizes, int n_in,
                              void* d_out, int out_size) {
    const float* lat = (const float*)d_in[0];
    const float* vqw = (const float*)d_in[1];
    const float* cb  = (const float*)d_in[2];
    float* out = (float*)d_out;

    static int s_attr = 0;
    if (!s_attr) {
        cudaFuncSetAttribute(k_gemm_cand,
                             cudaFuncAttributeMaxDynamicSharedMemorySize,
                             DSMEM_BYTES);
        s_attr = 1;
    }

    k_prep<<<192, 256>>>(lat, cb);
    k_gemm_cand<<<NROWS / MTILE, 256, DSMEM_BYTES>>>();
    k_refine<<<NROWS / 32, 256>>>(lat, cb);
    k_outloss<<<OUT_TENSOR_ELEMS / 256, 256>>>(lat, cb, out);
    k_final<<<1, 256>>>(vqw, out, out_size);
}

// round 17
// speedup vs baseline: 1.4451x; 1.0408x over previous
#include <cuda_runtime.h>
#include <cuda_fp16.h>
#include <cstdint>

// ===========================================================================
// Problem constants
// ===========================================================================
#define NROWS 16384          // B*X*Y*Z latent rows
#define DD    64
#define KCODES 8192
#define SS    4096           // X*Y*Z
#define BB    4
#define OUT_TENSOR_ELEMS (NROWS*DD)

#define MTILE 128            // rows per CTA
#define NT    128            // codes per iteration tile
#define NITER (KCODES/NT)    // 64
#define A_BYTES 16384        // 128 rows x 64 k x 1 term x 2B (fp16 fragments)
#define B_BYTES 16384        // 128 codes x 64 k x 1 term x 2B

// B pre-scaled by 2^13 (exact). Tracking metric: m = acc - 4096*cn
// (argmax m == argmin dist; scale 2^12 exact). Refine recomputes exact dist.
#define CN_SCALE (-4096.0f)

// dynamic smem (gemm): A 16K | B x3 16K | CN x3 512B
#define SM_A   0
#define SM_B(s)  (16384 + (s) * 16384)
#define SM_CN(s) (65536 + (s) * 512)
#define DSMEM_BYTES 67072

// ===========================================================================
// Device scratch (allocation-free rule)
// ===========================================================================
__device__ float g_rn[NROWS];
__device__ float g_cbn[KCODES];
__device__ uint4 g_latfrag[(NROWS / MTILE) * (A_BYTES / 16)];  // 2 MB
__device__ uint4 g_cbfrag[NITER * (B_BYTES / 16)];             // 1 MB
__device__ int2  g_cand[NROWS * 8];   // per row: 8 thread-slots x best-2 idx
__device__ int   g_idx[NROWS];
__device__ float g_losspart[256];

// ===========================================================================
// Helpers
// ===========================================================================
__device__ __forceinline__ uint32_t smem_u32(const void* p) {
    uint32_t a;
    asm("{ .reg .u64 t; cvta.to.shared.u64 t, %1; cvt.u32.u64 %0, t; }"
        : "=r"(a) : "l"(p));
    return a;
}
__device__ __forceinline__ void cp16(uint32_t dst, const void* src) {
    asm volatile("cp.async.cg.shared.global [%0], [%1], 16;"
                 :: "r"(dst), "l"(src) : "memory");
}
__device__ __forceinline__ void cp4(uint32_t dst, const void* src) {
    asm volatile("cp.async.ca.shared.global [%0], [%1], 4;"
                 :: "r"(dst), "l"(src) : "memory");
}
#define CP_COMMIT() asm volatile("cp.async.commit_group;" ::: "memory")
#define CP_WAIT1()  asm volatile("cp.async.wait_group 1;" ::: "memory")
#define CP_WAIT2()  asm volatile("cp.async.wait_group 2;" ::: "memory")

// fp16 m16n8k16, f32 accumulate
__device__ __forceinline__ void mma_f16(float* c, const uint32_t* a,
                                        uint32_t b0, uint32_t b1) {
    asm volatile(
        "mma.sync.aligned.m16n8k16.row.col.f32.f16.f16.f32 "
        "{%0,%1,%2,%3}, {%4,%5,%6,%7}, {%8,%9}, {%0,%1,%2,%3};"
        : "+f"(c[0]), "+f"(c[1]), "+f"(c[2]), "+f"(c[3])
        : "r"(a[0]), "r"(a[1]), "r"(a[2]), "r"(a[3]), "r"(b0), "r"(b1));
}

__device__ __forceinline__ uint32_t pack2h(float a, float b) {
    __half ha = __float2half_rn(a);
    __half hb = __float2half_rn(b);
    return (uint32_t)__half_as_ushort(ha) |
           ((uint32_t)__half_as_ushort(hb) << 16);
}

// ===========================================================================
// K_prep: merged prepA (CTAs 0..127) + prepB (CTAs 128..191).  [R11 verbatim]
// ===========================================================================
__global__ void k_prep(const float* __restrict__ lat,
                       const float* __restrict__ cb) {
    __shared__ float ts[128][65];
    int tid = threadIdx.x;

    if (blockIdx.x < 128) {
        int cta = blockIdx.x;
        int b = cta >> 5;
        int s0 = (cta & 31) * 128;

        {
            int d = tid >> 2;
            int sc = (tid & 3) * 32;
            const float4* src =
                (const float4*)(lat + ((size_t)b * DD + d) * SS + s0 + sc);
#pragma unroll
            for (int i = 0; i < 8; i++) {
                float4 v = src[i];
                ts[sc + 4 * i + 0][d] = v.x;
                ts[sc + 4 * i + 1][d] = v.y;
                ts[sc + 4 * i + 2][d] = v.z;
                ts[sc + 4 * i + 3][d] = v.w;
            }
        }
        __syncthreads();

        // row norm, replicating R1's packed accumulation order bit-for-bit
        if (tid < 128) {
            float rl[4] = {0.f, 0.f, 0.f, 0.f};
            float rh[4] = {0.f, 0.f, 0.f, 0.f};
#pragma unroll
            for (int m = 0; m < 8; m++) {
#pragma unroll
                for (int j = 0; j < 4; j++) {
                    float xl = ts[tid][8 * m + 2 * j];
                    float xh = ts[tid][8 * m + 2 * j + 1];
                    rl[j] = fmaf(xl, xl, rl[j]);
                    rh[j] = fmaf(xh, xh, rh[j]);
                }
            }
            float slo = (rl[0] + rl[1]) + (rl[2] + rl[3]);
            float shi = (rh[0] + rh[1]) + (rh[2] + rh[3]);
            g_rn[cta * MTILE + tid] = slo + shi;
        }

        // A fragments (term 1 only): blocks (wm:4)(s:4)(i:2) x 32 lanes
#pragma unroll
        for (int f4 = 0; f4 < 4; f4++) {
            int f = f4 * 256 + tid;
            int wm = f >> 8;
            int s = (f >> 6) & 3;
            int ii = (f >> 5) & 1;
            int lane = f & 31;
            int r0 = wm * 32 + ii * 16 + (lane >> 2);
            int k0 = s * 16 + (lane & 3) * 2;
            uint4 o;
            uint32_t* po = &o.x;
#pragma unroll
            for (int q = 0; q < 4; q++) {
                int dr = (q & 1) * 8;
                int dk = (q >> 1) * 8;
                po[q] = pack2h(ts[r0 + dr][k0 + dk], ts[r0 + dr][k0 + dk + 1]);
            }
            g_latfrag[cta * 1024 + f] = o;
        }
    } else {
        int tile = blockIdx.x - 128;
        int kc0 = tile * NT;

        {
            int code = tid >> 1;
            int half = tid & 1;
            const float4* src =
                (const float4*)(cb + (size_t)(kc0 + code) * DD) + half * 8;
#pragma unroll
            for (int i = 0; i < 8; i++) {
                float4 v = src[i];
                ts[code][half * 32 + 4 * i + 0] = v.x;
                ts[code][half * 32 + 4 * i + 1] = v.y;
                ts[code][half * 32 + 4 * i + 2] = v.z;
                ts[code][half * 32 + 4 * i + 3] = v.w;
            }
        }
        __syncthreads();

        if (tid < 128) {
            float a[4] = {0.f, 0.f, 0.f, 0.f};
#pragma unroll
            for (int i = 0; i < 16; i++) {
#pragma unroll
                for (int j = 0; j < 4; j++) {
                    float v = ts[tid][4 * i + j];
                    a[j] = fmaf(v, v, a[j]);
                }
            }
            g_cbn[kc0 + tid] = (a[0] + a[1]) + (a[2] + a[3]);
        }

        // B fragments (term 1 only, scaled 2^13): blocks (wn:2)(s:4)(p:4)
#pragma unroll
        for (int f4 = 0; f4 < 4; f4++) {
            int f = f4 * 256 + tid;
            int wn = f >> 9;
            int s = (f >> 7) & 3;
            int p = (f >> 5) & 3;
            int lane = f & 31;
            int g = lane >> 2;
            int k0 = s * 16 + (lane & 3) * 2;
            uint4 o;
            uint32_t* po = &o.x;
#pragma unroll
            for (int c = 0; c < 4; c++) {
                int j = 2 * p + (c >> 1);
                int dk = ((c & 1) ? 8 : 0);
                int code = wn * 64 + j * 8 + g;
                po[c] = pack2h(ts[code][k0 + dk] * 8192.0f,
                               ts[code][k0 + dk + 1] * 8192.0f);
            }
            g_cbfrag[tile * 1024 + f] = o;
        }
    }
}

// ===========================================================================
// K1: phase-1 fp16 GEMM + best-2 candidate tracking.  [R14 verbatim]
// ===========================================================================
__global__ void __launch_bounds__(256, 1) k_gemm_cand() {
    extern __shared__ char sm[];
    uint32_t sbase = smem_u32(sm);
    int tid = threadIdx.x;
    int lane = tid & 31;
    int wid = tid >> 5;
    int wm = wid >> 1;               // rows wm*32..+32
    int wn = wid & 1;                // cols wn*64..+64
    int cta = blockIdx.x;

    // ---- prologue: A (g0), B tile0+CN0 (g1), B tile1+CN1 (g2) ----
    {
        const char* asrc = (const char*)g_latfrag + (size_t)cta * A_BYTES;
#pragma unroll
        for (int c = 0; c < 4; c++)
            cp16(sbase + SM_A + (c * 256 + tid) * 16, asrc + (c * 256 + tid) * 16);
        CP_COMMIT();
        const char* bsrc = (const char*)g_cbfrag;
#pragma unroll
        for (int c = 0; c < 4; c++)
            cp16(sbase + SM_B(0) + (c * 256 + tid) * 16, bsrc + (c * 256 + tid) * 16);
        if (tid < 128) cp4(sbase + SM_CN(0) + tid * 4, g_cbn + tid);
        CP_COMMIT();
#pragma unroll
        for (int c = 0; c < 4; c++)
            cp16(sbase + SM_B(1) + (c * 256 + tid) * 16,
                 bsrc + B_BYTES + (c * 256 + tid) * 16);
        if (tid < 128) cp4(sbase + SM_CN(1) + tid * 4, g_cbn + 128 + tid);
        CP_COMMIT();
    }

    // ---- wait for A, cache 8 A fragments (term 1) in registers ----
    CP_WAIT2();
    __syncthreads();
    uint32_t af[4][2][4];            // [s][i][4regs]
    {
        uint32_t a_base = sbase + SM_A + (uint32_t)wm * 4096 + lane * 16;
#pragma unroll
        for (int s = 0; s < 4; s++)
#pragma unroll
            for (int i = 0; i < 2; i++) {
                asm volatile("ld.shared.v4.b32 {%0,%1,%2,%3}, [%4];"
                    : "=r"(af[s][i][0]), "=r"(af[s][i][1]),
                      "=r"(af[s][i][2]), "=r"(af[s][i][3])
                    : "r"(a_base + (uint32_t)(s * 2 + i) * 512u));
            }
    }

    // best-2 per slot (metric m, maximized; index kept for refine)
    float v1[4] = {-3.4e38f, -3.4e38f, -3.4e38f, -3.4e38f};
    float v2[4] = {-3.4e38f, -3.4e38f, -3.4e38f, -3.4e38f};
    int   i1[4] = {0, 0, 0, 0};
    int   i2[4] = {0, 0, 0, 0};
    uint32_t cn_off = (uint32_t)(wn * 64 + (lane & 3) * 2) * 4;

    int sel = 0;
    for (int t = 0; t < NITER; t++) {
        CP_WAIT1();
        __syncthreads();

        int psel = sel + 2; if (psel >= 3) psel -= 3;
        if (t + 2 < NITER) {
            const char* bsrc = (const char*)g_cbfrag + (size_t)(t + 2) * B_BYTES;
            uint32_t dst = sbase + SM_B(psel);
#pragma unroll
            for (int c = 0; c < 4; c++)
                cp16(dst + (c * 256 + tid) * 16, bsrc + (c * 256 + tid) * 16);
            if (tid < 128)
                cp4(sbase + SM_CN(psel) + tid * 4, g_cbn + (t + 2) * NT + tid);
        }
        CP_COMMIT();

        uint32_t b_base = sbase + SM_B(sel) + (uint32_t)wn * 8192 + lane * 16;
        uint32_t cn_base = sbase + SM_CN(sel) + cn_off;

        float acc[2][8][4];
#pragma unroll
        for (int i = 0; i < 2; i++)
#pragma unroll
            for (int j = 0; j < 8; j++)
#pragma unroll
                for (int v = 0; v < 4; v++) acc[i][j][v] = 0.f;

#pragma unroll
        for (int s = 0; s < 4; s++) {
            uint32_t bw[4][4];
#pragma unroll
            for (int p = 0; p < 4; p++)
                asm volatile("ld.shared.v4.b32 {%0,%1,%2,%3}, [%4];"
                    : "=r"(bw[p][0]), "=r"(bw[p][1]),
                      "=r"(bw[p][2]), "=r"(bw[p][3])
                    : "r"(b_base + (uint32_t)(s * 4 + p) * 512u));
#pragma unroll
            for (int p = 0; p < 4; p++) {
                mma_f16(acc[0][2 * p],     af[s][0], bw[p][0], bw[p][1]);
                mma_f16(acc[0][2 * p + 1], af[s][0], bw[p][2], bw[p][3]);
                mma_f16(acc[1][2 * p],     af[s][1], bw[p][0], bw[p][1]);
                mma_f16(acc[1][2 * p + 1], af[s][1], bw[p][2], bw[p][3]);
            }
        }

        // best-2 tracking: max of m = fmaf(-4096, cn, acc); rare-branch path
        int kb = t * NT + wn * 64 + 2 * (lane & 3);
#pragma unroll
        for (int j = 0; j < 8; j++) {
            float2 cn2;
            asm volatile("ld.shared.v2.b32 {%0,%1}, [%2];"
                : "=f"(cn2.x), "=f"(cn2.y) : "r"(cn_base + j * 32u));
            int kbj = kb + j * 8;
#pragma unroll
            for (int i = 0; i < 2; i++) {
#pragma unroll
                for (int v = 0; v < 4; v++) {
                    float cn = (v & 1) ? cn2.y : cn2.x;
                    int slot = i * 2 + (v >> 1);
                    float m = fmaf(CN_SCALE, cn, acc[i][j][v]);
                    int idx = kbj + (v & 1);
                    if (m > v2[slot]) {
                        if (m > v1[slot]) {
                            v2[slot] = v1[slot]; i2[slot] = i1[slot];
                            v1[slot] = m;        i1[slot] = idx;
                        } else {
                            v2[slot] = m;        i2[slot] = idx;
                        }
                    }
                }
            }
        }

        sel++; if (sel >= 3) sel -= 3;
    }

    // ---- emit candidates: per slot, 2 indices ----
    int slotcol = wn * 4 + (lane & 3);
#pragma unroll
    for (int i = 0; i < 2; i++)
#pragma unroll
        for (int h = 0; h < 2; h++) {
            int row = cta * MTILE + wm * 32 + i * 16 + (lane >> 2) + h * 8;
            int slot = i * 2 + h;
            g_cand[row * 8 + slotcol] = make_int2(i1[slot], i2[slot]);
        }
}

// ===========================================================================
// K2: exact refinement, 8 threads per row.  [R12 verbatim]
// ===========================================================================
__global__ void __launch_bounds__(256) k_refine(const float* __restrict__ lat,
                                                const float* __restrict__ cb) {
    int tid = threadIdx.x;
    int grp = tid & 7;                       // candidate slot 0..7
    int n = blockIdx.x * 32 + (tid >> 3);    // row
    int s = n & (SS - 1);
    int b = n >> 12;

    float x[DD];
#pragma unroll
    for (int d = 0; d < DD; d++)
        x[d] = lat[((size_t)b * DD + d) * SS + s];

    float rn = g_rn[n];
    int2 c2 = g_cand[n * 8 + grp];

    unsigned long long best = 0xFFFFFFFFFFFFFFFFull;
#pragma unroll
    for (int c = 0; c < 2; c++) {
        int idx = (c == 0) ? c2.x : c2.y;
        const float4* e4 = (const float4*)(cb + (size_t)idx * DD);
        float a0 = 0.f, a1 = 0.f, a2 = 0.f, a3 = 0.f;
#pragma unroll
        for (int q = 0; q < 16; q++) {
            float4 e = e4[q];
            a0 = fmaf(x[4 * q + 0], e.x, a0);
            a1 = fmaf(x[4 * q + 1], e.y, a1);
            a2 = fmaf(x[4 * q + 2], e.z, a2);
            a3 = fmaf(x[4 * q + 3], e.w, a3);
        }
        float dot = (a0 + a1) + (a2 + a3);
        float dist = fmaf(-2.f, dot, rn + g_cbn[idx]);
        unsigned long long key =
            ((unsigned long long)__float_as_uint(dist) << 32) | (unsigned)idx;
        if (key < best) best = key;
    }

#pragma unroll
    for (int o = 4; o > 0; o >>= 1) {
        unsigned long long other = __shfl_xor_sync(0xffffffffu, best, o);
        if (other < best) best = other;
    }
    if (grp == 0) g_idx[n] = (int)(unsigned)best;
}

// ===========================================================================
// K3: output gather + loss partials, sector-perfect gather layout.
// 256 blocks; block = (batch b, 64-s tile, all 64 d). Warp = 16-d strip x
// 32 consecutive s. Thread = one row n x 16 d -> 4 float4 cb loads (64B
// contiguous). lat loads / out stores coalesced per d.
// ===========================================================================
__global__ void __launch_bounds__(256) k_outloss(const float* __restrict__ lat,
                                                 const float* __restrict__ cb,
                                                 float* __restrict__ out) {
    int blk = blockIdx.x;                 // 0..255
    int b = blk >> 6;
    int s0 = (blk & 63) * 64;
    int w = threadIdx.x >> 5;
    int lane = threadIdx.x & 31;
    int s = s0 + (w & 1) * 32 + lane;
    int d0 = (w >> 1) * 16;
    int n = b * SS + s;
    int idx = g_idx[n];

    const float4* e4 = (const float4*)(cb + (size_t)idx * DD + d0);
    float acc = 0.f;
#pragma unroll
    for (int q = 0; q < 4; q++) {
        float4 ev = e4[q];
        const float* pe = &ev.x;
#pragma unroll
        for (int k = 0; k < 4; k++) {
            int d = d0 + q * 4 + k;
            size_t a = ((size_t)(b * DD + d)) * SS + s;
            float qv = pe[k];
            float l = lat[a];
            out[a] = qv;
            float df = qv - l;
            acc = fmaf(df, df, acc);
        }
    }

    // warp reduce + cross-warp partial (per-block sum)
#pragma unroll
    for (int o = 16; o > 0; o >>= 1)
        acc += __shfl_down_sync(0xffffffffu, acc, o);
    __shared__ float red[8];
    if (lane == 0) red[w] = acc;
    __syncthreads();
    if (threadIdx.x < 32) {
        float x = (threadIdx.x < 8) ? red[threadIdx.x] : 0.f;
#pragma unroll
        for (int o = 4; o > 0; o >>= 1) x += __shfl_down_sync(0xffffffffu, x, o);
        if (threadIdx.x == 0) g_losspart[blk] = x;
    }
}

// ===========================================================================
// K4: final fixed-order reduce over 256 partials
// ===========================================================================
__global__ void k_final(const float* __restrict__ vqw,
                        float* __restrict__ out, int out_size) {
    __shared__ float sm2[256];
    int tid = threadIdx.x;
    sm2[tid] = g_losspart[tid];
    __syncthreads();
    for (int o = 128; o > 0; o >>= 1) {
        if (tid < o) sm2[tid] += sm2[tid + o];
        __syncthreads();
    }
    if (tid == 0 && out_size > OUT_TENSOR_ELEMS) {
        float w = vqw[0];
        out[out_size - 1] = sm2[0] * (1.f + w) * (1.f / (float)OUT_TENSOR_ELEMS);
    }
}

// ===========================================================================
extern "C" void kernel_launch(void* const* d_in, const int* in_sizes, int n_in,
                              void* d_out, int out_size) {
    const float* lat = (const float*)d_in[0];
    const float* vqw = (const float*)d_in[1];
    const float* cb  = (const float*)d_in[2];
    float* out = (float*)d_out;

    static int s_attr = 0;
    if (!s_attr) {
        cudaFuncSetAttribute(k_gemm_cand,
                             cudaFuncAttributeMaxDynamicSharedMemorySize,
                             DSMEM_BYTES);
        s_attr = 1;
    }

    k_prep<<<192, 256>>>(lat, cb);
    k_gemm_cand<<<NROWS / MTILE, 256, DSMEM_BYTES>>>();
    k_refine<<<NROWS / 32, 256>>>(lat, cb);
    k_outloss<<<256, 256>>>(lat, cb, out);
    k_final<<<1, 256>>>(vqw, out, out_size);
}